// round 4
// baseline (speedup 1.0000x reference)
#include <cuda_runtime.h>
#include <cuda_bf16.h>
#include <cstdint>
#include <math.h>

// Problem constants
#define BTOT 32768      // BS*T = 128*256
#define SD   512        // STATE_DIM
#define EMB  32
#define HYP  256

// ---------------- global scratch (no allocations allowed) ----------------
__device__ float g_Y [(size_t)BTOT * SD];    // per-row embedded state y (B,512)
__device__ float g_H1[(size_t)BTOT * HYP];   // relu(y@W1a+b1a)
__device__ float g_HF[(size_t)BTOT * HYP];   // relu(y@Wfa+bfa)
__device__ float g_W1[(size_t)BTOT * 256];   // abs(H1@W1b+b1b)
__device__ float g_B1[(size_t)BTOT * EMB];   // y@Wb1+bb1
__device__ float g_Hv[(size_t)BTOT * EMB];   // relu(y@Wv1+bv1)
__device__ float g_WF[(size_t)BTOT * EMB];   // abs(HF@Wfb+bfb)

__device__ __forceinline__ uint32_t smem_u32(const void* p) {
    return (uint32_t)__cvta_generic_to_shared(p);
}

#define LDSM4(r0, r1, r2, r3, addr) \
    asm volatile("ldmatrix.sync.aligned.m8n8.x4.shared.b16 {%0,%1,%2,%3}, [%4];" \
        : "=r"(r0), "=r"(r1), "=r"(r2), "=r"(r3) : "r"(addr))

#define MMA_BF16(c, a, b) \
    asm volatile("mma.sync.aligned.m16n8k16.row.col.f32.bf16.bf16.f32 " \
        "{%0,%1,%2,%3}, {%4,%5,%6,%7}, {%8,%9}, {%0,%1,%2,%3};" \
        : "+f"((c)[0]), "+f"((c)[1]), "+f"((c)[2]), "+f"((c)[3]) \
        : "r"((a)[0]), "r"((a)[1]), "r"((a)[2]), "r"((a)[3]), \
          "r"((b)[0]), "r"((b)[1]))

// =========================================================================
// K1: per-row token embed (unchanged from passing R2 kernel)
// =========================================================================
__global__ __launch_bounds__(64) void k1_embed(
    const float* __restrict__ states,
    const float* __restrict__ Wt, const float* __restrict__ bt,
    const float* __restrict__ Wy, const float* __restrict__ by)
{
    __shared__ float s_sm[8 * 520];
    __shared__ float wt_sm[64 * 32];
    __shared__ float wy_sm[32 * 64];
    __shared__ float bt_sm[32];
    __shared__ float by_sm[64];

    const int tid = threadIdx.x;
    {
        const float4* Wt4 = (const float4*)Wt;
        float4* d = (float4*)wt_sm;
        for (int i = tid; i < 512; i += 64) d[i] = Wt4[i];
        const float4* Wy4 = (const float4*)Wy;
        float4* d2 = (float4*)wy_sm;
        for (int i = tid; i < 512; i += 64) d2[i] = Wy4[i];
        if (tid < 32) bt_sm[tid] = bt[tid];
        by_sm[tid] = by[tid];
    }
    {
        const float4* S4 = (const float4*)(states + (size_t)blockIdx.x * 8 * SD);
        #pragma unroll
        for (int i = 0; i < 16; i++) {
            int f4 = tid + i * 64;
            float4 v = S4[f4];
            int row = f4 >> 7;
            int e0  = (f4 & 127) * 4;
            int a   = e0 >> 6;
            int k   = e0 & 63;
            float* dp = &s_sm[row * 520 + a * 65 + k];
            dp[0] = v.x; dp[1] = v.y; dp[2] = v.z; dp[3] = v.w;
        }
    }
    __syncthreads();

    const int r = tid >> 3, a = tid & 7;
    const float* srow = &s_sm[r * 520 + a * 65];

    float e[32];
    #pragma unroll
    for (int j = 0; j < 32; j++) e[j] = bt_sm[j];
    #pragma unroll 8
    for (int k = 0; k < 64; k++) {
        float sv = srow[k];
        const float4* wrow = (const float4*)&wt_sm[k * 32];
        #pragma unroll
        for (int j4 = 0; j4 < 8; j4++) {
            float4 w = wrow[j4];
            e[j4*4+0] += sv * w.x; e[j4*4+1] += sv * w.y;
            e[j4*4+2] += sv * w.z; e[j4*4+3] += sv * w.w;
        }
    }
    #pragma unroll
    for (int j = 0; j < 32; j++) e[j] = fmaxf(e[j], 0.f);

    float y[64];
    #pragma unroll
    for (int c = 0; c < 64; c++) y[c] = by_sm[c];
    #pragma unroll 4
    for (int j = 0; j < 32; j++) {
        float ev = e[j];
        const float4* wrow = (const float4*)&wy_sm[j * 64];
        #pragma unroll
        for (int c4 = 0; c4 < 16; c4++) {
            float4 w = wrow[c4];
            y[c4*4+0] += ev * w.x; y[c4*4+1] += ev * w.y;
            y[c4*4+2] += ev * w.z; y[c4*4+3] += ev * w.w;
        }
    }
    size_t row_g = (size_t)blockIdx.x * 8 + r;
    float4* out = (float4*)(g_Y + row_g * SD + a * 64);
    #pragma unroll
    for (int c4 = 0; c4 < 16; c4++) {
        float4 o;
        o.x = fmaxf(y[c4*4+0], 0.f); o.y = fmaxf(y[c4*4+1], 0.f);
        o.z = fmaxf(y[c4*4+2], 0.f); o.w = fmaxf(y[c4*4+3], 0.f);
        out[c4] = o;
    }
}

// =========================================================================
// gemm_mma: bf16 mma.sync GEMM with hi/lo 3-product compensation.
// BM=128, BN=64, BK=32, 128 threads = 4 warps (warp tile 64x32).
// mode 0 (k2):  C(B,576) = Y(B,512) @ [W1a|Wfa|Wb1|Wv1]  -> H1/HF/B1/Hv
// mode 1 (k3):  blocks 0-3: W1(B,256) = abs(H1 @ W1b + b1b)
//               block  4  : WF(B,32)  = abs(HF @ Wfb + bfb)
// SMEM: A hi/lo [128][40] bf16, B hi/lo [64][40] bf16 (pitch 40 -> ldmatrix
// conflict-free: 80B row pitch gives distinct 128B phases for 8 rows).
// =========================================================================
#define PITCH 40

__global__ __launch_bounds__(128) void gemm_mma(
    int mode,
    const float* __restrict__ W1a, const float* __restrict__ b1a,
    const float* __restrict__ Wfa, const float* __restrict__ bfa,
    const float* __restrict__ Wb1, const float* __restrict__ bb1,
    const float* __restrict__ Wv1, const float* __restrict__ bv1,
    const float* __restrict__ W1b, const float* __restrict__ b1b,
    const float* __restrict__ Wfb, const float* __restrict__ bfb)
{
    __shared__ __align__(16) __nv_bfloat16 sAh[128 * PITCH];
    __shared__ __align__(16) __nv_bfloat16 sAl[128 * PITCH];
    __shared__ __align__(16) __nv_bfloat16 sBh[64 * PITCH];
    __shared__ __align__(16) __nv_bfloat16 sBl[64 * PITCH];

    const int tid  = threadIdx.x;
    const int wid  = tid >> 5;
    const int lane = tid & 31;
    const int wm   = wid >> 1;          // 0..1 : m-half (64 rows)
    const int wn   = wid & 1;           // 0..1 : n-half (32 cols)
    const int nbase = blockIdx.x * 64;
    const int m0    = blockIdx.y * 128;

    const float* Aptr; int lda, NC;
    if (mode == 0) { Aptr = g_Y; lda = 512; NC = 16; }
    else           { Aptr = (blockIdx.x == 4) ? g_HF : g_H1; lda = 256; NC = 8; }

    float acc[4][4][4];
    #pragma unroll
    for (int i = 0; i < 4; i++)
        #pragma unroll
        for (int j = 0; j < 4; j++)
            #pragma unroll
            for (int q = 0; q < 4; q++) acc[i][j][q] = 0.f;

    for (int c = 0; c < NC; ++c) {
        // ---- stage A chunk: 128 rows x 32 k, fp32 -> hi/lo bf16 ----
        const float* Asrc = Aptr + (size_t)m0 * lda + c * 32;
        #pragma unroll
        for (int i = 0; i < 8; i++) {
            int f4  = tid + i * 128;
            int row = f4 >> 3;
            int kk  = (f4 & 7) * 4;
            float4 v = *(const float4*)(Asrc + (size_t)row * lda + kk);
            __nv_bfloat162 h0, h1, l0, l1;
            h0.x = __float2bfloat16(v.x); h0.y = __float2bfloat16(v.y);
            h1.x = __float2bfloat16(v.z); h1.y = __float2bfloat16(v.w);
            l0.x = __float2bfloat16(v.x - __bfloat162float(h0.x));
            l0.y = __float2bfloat16(v.y - __bfloat162float(h0.y));
            l1.x = __float2bfloat16(v.z - __bfloat162float(h1.x));
            l1.y = __float2bfloat16(v.w - __bfloat162float(h1.y));
            int e = row * PITCH + kk;
            *(__nv_bfloat162*)&sAh[e]     = h0;
            *(__nv_bfloat162*)&sAh[e + 2] = h1;
            *(__nv_bfloat162*)&sAl[e]     = l0;
            *(__nv_bfloat162*)&sAl[e + 2] = l1;
        }
        // ---- stage B chunk: 64 n x 32 k (transpose-gather from weights) ----
        #pragma unroll
        for (int i = 0; i < 16; i++) {
            int idx = tid + i * 128;
            int n = idx & 63, k = idx >> 6;
            int ng = nbase + n;
            int kr = c * 32 + k;
            float v;
            if (mode == 0) {
                if (ng < 256)      v = W1a[(size_t)kr * 256 + ng];
                else if (ng < 512) v = Wfa[(size_t)kr * 256 + (ng - 256)];
                else if (ng < 544) v = Wb1[(size_t)kr * 32 + (ng - 512)];
                else               v = Wv1[(size_t)kr * 32 + (ng - 544)];
            } else {
                if (nbase < 256)   v = W1b[(size_t)kr * 256 + ng];
                else               v = (n < 32) ? Wfb[(size_t)kr * 32 + n] : 0.f;
            }
            __nv_bfloat16 h = __float2bfloat16(v);
            __nv_bfloat16 l = __float2bfloat16(v - __bfloat162float(h));
            sBh[n * PITCH + k] = h;
            sBl[n * PITCH + k] = l;
        }
        __syncthreads();

        // ---- compute: 2 k-steps of 16 ----
        const int g  = lane >> 3;
        const int li = lane & 7;
        #pragma unroll
        for (int ks = 0; ks < 2; ks++) {
            const int am = wm * 64 + (g & 1) * 8 + li;
            const int ak = (g >> 1) * 8 + ks * 16;
            const int bn = wn * 32 + (g >> 1) * 8 + li;
            const int bk = (g & 1) * 8 + ks * 16;

            uint32_t ah[4][4], al[4][4], bh[4][2], bl[4][2];
            #pragma unroll
            for (int mi = 0; mi < 4; mi++) {
                uint32_t a1 = smem_u32(&sAh[(am + mi * 16) * PITCH + ak]);
                LDSM4(ah[mi][0], ah[mi][1], ah[mi][2], ah[mi][3], a1);
                uint32_t a2 = smem_u32(&sAl[(am + mi * 16) * PITCH + ak]);
                LDSM4(al[mi][0], al[mi][1], al[mi][2], al[mi][3], a2);
            }
            #pragma unroll
            for (int bp = 0; bp < 2; bp++) {
                uint32_t a1 = smem_u32(&sBh[(bn + bp * 16) * PITCH + bk]);
                LDSM4(bh[2*bp][0], bh[2*bp][1], bh[2*bp+1][0], bh[2*bp+1][1], a1);
                uint32_t a2 = smem_u32(&sBl[(bn + bp * 16) * PITCH + bk]);
                LDSM4(bl[2*bp][0], bl[2*bp][1], bl[2*bp+1][0], bl[2*bp+1][1], a2);
            }
            #pragma unroll
            for (int mi = 0; mi < 4; mi++)
                #pragma unroll
                for (int ni = 0; ni < 4; ni++) {
                    MMA_BF16(acc[mi][ni], ah[mi], bh[ni]);
                    MMA_BF16(acc[mi][ni], ah[mi], bl[ni]);
                    MMA_BF16(acc[mi][ni], al[mi], bh[ni]);
                }
        }
        __syncthreads();
    }

    // ---- epilogue: bias + activation, direct float2 stores ----
    #pragma unroll
    for (int mi = 0; mi < 4; mi++) {
        #pragma unroll
        for (int ni = 0; ni < 4; ni++) {
            int m  = m0 + wm * 64 + mi * 16 + (lane >> 2);
            int ng = nbase + wn * 32 + ni * 8 + 2 * (lane & 3);
            #pragma unroll
            for (int half = 0; half < 2; half++) {
                int mm = m + half * 8;
                float x0 = acc[mi][ni][half * 2 + 0];
                float x1 = acc[mi][ni][half * 2 + 1];
                if (mode == 0) {
                    if (ng < 256) {
                        float2 b = *(const float2*)&b1a[ng];
                        float2 o = make_float2(fmaxf(x0 + b.x, 0.f), fmaxf(x1 + b.y, 0.f));
                        *(float2*)&g_H1[(size_t)mm * 256 + ng] = o;
                    } else if (ng < 512) {
                        int nl = ng - 256;
                        float2 b = *(const float2*)&bfa[nl];
                        float2 o = make_float2(fmaxf(x0 + b.x, 0.f), fmaxf(x1 + b.y, 0.f));
                        *(float2*)&g_HF[(size_t)mm * 256 + nl] = o;
                    } else if (ng < 544) {
                        int nl = ng - 512;
                        float2 b = *(const float2*)&bb1[nl];
                        float2 o = make_float2(x0 + b.x, x1 + b.y);
                        *(float2*)&g_B1[(size_t)mm * 32 + nl] = o;
                    } else {
                        int nl = ng - 544;
                        float2 b = *(const float2*)&bv1[nl];
                        float2 o = make_float2(fmaxf(x0 + b.x, 0.f), fmaxf(x1 + b.y, 0.f));
                        *(float2*)&g_Hv[(size_t)mm * 32 + nl] = o;
                    }
                } else {
                    if (nbase < 256) {
                        float2 b = *(const float2*)&b1b[ng];
                        float2 o = make_float2(fabsf(x0 + b.x), fabsf(x1 + b.y));
                        *(float2*)&g_W1[(size_t)mm * 256 + ng] = o;
                    } else {
                        int nl = ng - 256;
                        if (nl < 32) {
                            float2 b = *(const float2*)&bfb[nl];
                            float2 o = make_float2(fabsf(x0 + b.x), fabsf(x1 + b.y));
                            *(float2*)&g_WF[(size_t)mm * 32 + nl] = o;
                        }
                    }
                }
            }
        }
    }
}

// =========================================================================
// K4: final fused epilogue. One warp per row; lane = EMB index e.
// =========================================================================
__device__ __forceinline__ float wred(float v) {
    #pragma unroll
    for (int o = 16; o > 0; o >>= 1) v += __shfl_xor_sync(0xFFFFFFFFu, v, o);
    return v;
}

__global__ __launch_bounds__(256) void k4_final(
    const float* __restrict__ agent_qs,
    const float* __restrict__ Wv2, const float* __restrict__ bv2,
    float* __restrict__ out)
{
    const int w = threadIdx.x >> 5, lane = threadIdx.x & 31;
    const size_t r = (size_t)blockIdx.x * 8 + w;

    const float wv2v = Wv2[lane];

    float q[8];
    #pragma unroll
    for (int a = 0; a < 8; a++) q[a] = agent_qs[r * 8 + a];

    float w1r[8];
    const float* w1p = g_W1 + r * 256;
    #pragma unroll
    for (int a = 0; a < 8; a++) w1r[a] = w1p[a * 32 + lane];

    float x = g_B1[r * 32 + lane];
    #pragma unroll
    for (int a = 0; a < 8; a++) x += q[a] * w1r[a];
    const float h    = (x > 0.f) ? x : expm1f(x);
    const float delu = (h < 0.f) ? expf(h) : 1.f;

    const float wf = g_WF[r * 32 + lane];
    const float hv = g_Hv[r * 32 + lane];

    const float vsum = wred(hv * wv2v);
    const float qt   = wred(h * wf);
    if (lane == 0) out[r] = qt + vsum + bv2[0];

    const float t = delu * wf;
    float* gout = out + BTOT;
    #pragma unroll
    for (int a = 0; a < 8; a++) {
        float s = wred(w1r[a] * t);
        if (lane == a) gout[r * 8 + a] = s;
    }
}

// =========================================================================
extern "C" void kernel_launch(void* const* d_in, const int* in_sizes, int n_in,
                              void* d_out, int out_size)
{
    (void)in_sizes; (void)n_in; (void)out_size;
    const float* agent_qs = (const float*)d_in[0];
    const float* states = (const float*)d_in[2];   // d_in[1]=hist, d_in[3]=obs unused
    const float* W_tok  = (const float*)d_in[4];
    const float* b_tok  = (const float*)d_in[5];
    const float* W_yfc  = (const float*)d_in[6];
    const float* b_yfc  = (const float*)d_in[7];
    const float* W1a    = (const float*)d_in[8];
    const float* b1a    = (const float*)d_in[9];
    const float* W1b    = (const float*)d_in[10];
    const float* b1b    = (const float*)d_in[11];
    const float* Wfa    = (const float*)d_in[12];
    const float* bfa    = (const float*)d_in[13];
    const float* Wfb    = (const float*)d_in[14];
    const float* bfb    = (const float*)d_in[15];
    const float* Wb1    = (const float*)d_in[16];
    const float* bb1    = (const float*)d_in[17];
    const float* Wv1    = (const float*)d_in[18];
    const float* bv1    = (const float*)d_in[19];
    const float* Wv2    = (const float*)d_in[20];
    const float* bv2    = (const float*)d_in[21];
    float* out = (float*)d_out;

    k1_embed<<<BTOT / 8, 64>>>(states, W_tok, b_tok, W_yfc, b_yfc);
    gemm_mma<<<dim3(9, BTOT / 128), 128>>>(0,
        W1a, b1a, Wfa, bfa, Wb1, bb1, Wv1, bv1, W1b, b1b, Wfb, bfb);
    gemm_mma<<<dim3(5, BTOT / 128), 128>>>(1,
        W1a, b1a, Wfa, bfa, Wb1, bb1, Wv1, bv1, W1b, b1b, Wfb, bfb);
    k4_final<<<BTOT / 8, 256>>>(agent_qs, Wv2, bv2, out);
}

// round 5
// speedup vs baseline: 2.3294x; 2.3294x over previous
#include <cuda_runtime.h>
#include <cuda_bf16.h>
#include <cstdint>
#include <math.h>

// Problem constants
#define BTOT 32768      // BS*T = 128*256
#define SD   512        // STATE_DIM
#define EMB  32
#define HYP  256

// ---------------- global scratch (no allocations allowed) ----------------
__device__ __nv_bfloat16 g_Yh [(size_t)BTOT * SD];   // y hi (bf16)
__device__ __nv_bfloat16 g_Yl [(size_t)BTOT * SD];   // y lo (bf16)
__device__ __nv_bfloat16 g_H1h[(size_t)BTOT * HYP];
__device__ __nv_bfloat16 g_H1l[(size_t)BTOT * HYP];
__device__ __nv_bfloat16 g_HFh[(size_t)BTOT * HYP];
__device__ __nv_bfloat16 g_HFl[(size_t)BTOT * HYP];
__device__ float g_W1[(size_t)BTOT * 256];           // abs(H1@W1b+b1b)
__device__ float g_B1[(size_t)BTOT * EMB];           // y@Wb1+bb1
__device__ float g_Hv[(size_t)BTOT * EMB];           // relu(y@Wv1+bv1)
__device__ float g_WF[(size_t)BTOT * EMB];           // abs(HF@Wfb+bfb)

// transposed+split weights:  [n][k] bf16
__device__ __nv_bfloat16 g_WT0h[576 * 512];          // [W1a|Wfa|Wb1|Wv1]^T
__device__ __nv_bfloat16 g_WT0l[576 * 512];
__device__ __nv_bfloat16 g_WT1h[320 * 256];          // [W1b|Wfb|pad]^T
__device__ __nv_bfloat16 g_WT1l[320 * 256];

__device__ __forceinline__ uint32_t smem_u32(const void* p) {
    return (uint32_t)__cvta_generic_to_shared(p);
}

#define LDSM4(r0, r1, r2, r3, addr) \
    asm volatile("ldmatrix.sync.aligned.m8n8.x4.shared.b16 {%0,%1,%2,%3}, [%4];" \
        : "=r"(r0), "=r"(r1), "=r"(r2), "=r"(r3) : "r"(addr))

#define MMA_BF16(c, a, b) \
    asm volatile("mma.sync.aligned.m16n8k16.row.col.f32.bf16.bf16.f32 " \
        "{%0,%1,%2,%3}, {%4,%5,%6,%7}, {%8,%9}, {%0,%1,%2,%3};" \
        : "+f"((c)[0]), "+f"((c)[1]), "+f"((c)[2]), "+f"((c)[3]) \
        : "r"((a)[0]), "r"((a)[1]), "r"((a)[2]), "r"((a)[3]), \
          "r"((b)[0]), "r"((b)[1]))

#define CP16(dst, src) \
    asm volatile("cp.async.cg.shared.global [%0], [%1], 16;" :: "r"(dst), "l"(src))
#define CP_COMMIT() asm volatile("cp.async.commit_group;" ::: "memory")
#define CP_WAIT(n)  asm volatile("cp.async.wait_group %0;" :: "n"(n) : "memory")

__device__ __forceinline__ void bf_split(float v, __nv_bfloat16& h, __nv_bfloat16& l) {
    h = __float2bfloat16(v);
    l = __float2bfloat16(v - __bfloat162float(h));
}

// =========================================================================
// prep: transpose + hi/lo-split all GEMM weights (runs once per launch, tiny)
// =========================================================================
__global__ __launch_bounds__(256) void prep_split(
    const float* __restrict__ W1a, const float* __restrict__ Wfa,
    const float* __restrict__ Wb1, const float* __restrict__ Wv1,
    const float* __restrict__ W1b, const float* __restrict__ Wfb)
{
    int idx = blockIdx.x * 256 + threadIdx.x;
    if (idx < 576 * 512) {
        int n = idx >> 9, k = idx & 511;
        float v;
        if (n < 256)      v = W1a[k * 256 + n];
        else if (n < 512) v = Wfa[k * 256 + (n - 256)];
        else if (n < 544) v = Wb1[k * 32 + (n - 512)];
        else              v = Wv1[k * 32 + (n - 544)];
        __nv_bfloat16 h, l; bf_split(v, h, l);
        g_WT0h[idx] = h; g_WT0l[idx] = l;
    }
    int idx2 = idx - 576 * 512;
    if (idx2 >= 0 && idx2 < 320 * 256) {
        int n = idx2 >> 8, k = idx2 & 255;
        float v = 0.f;
        if (n < 256)      v = W1b[k * 256 + n];
        else if (n < 288) v = Wfb[k * 32 + (n - 256)];
        __nv_bfloat16 h, l; bf_split(v, h, l);
        g_WT1h[idx2] = h; g_WT1l[idx2] = l;
    }
}

// =========================================================================
// K1: per-row token embed; now emits Y as bf16 hi/lo
// =========================================================================
__global__ __launch_bounds__(64) void k1_embed(
    const float* __restrict__ states,
    const float* __restrict__ Wt, const float* __restrict__ bt,
    const float* __restrict__ Wy, const float* __restrict__ by)
{
    __shared__ float s_sm[8 * 520];
    __shared__ float wt_sm[64 * 32];
    __shared__ float wy_sm[32 * 64];
    __shared__ float bt_sm[32];
    __shared__ float by_sm[64];

    const int tid = threadIdx.x;
    {
        const float4* Wt4 = (const float4*)Wt;
        float4* d = (float4*)wt_sm;
        for (int i = tid; i < 512; i += 64) d[i] = Wt4[i];
        const float4* Wy4 = (const float4*)Wy;
        float4* d2 = (float4*)wy_sm;
        for (int i = tid; i < 512; i += 64) d2[i] = Wy4[i];
        if (tid < 32) bt_sm[tid] = bt[tid];
        by_sm[tid] = by[tid];
    }
    {
        const float4* S4 = (const float4*)(states + (size_t)blockIdx.x * 8 * SD);
        #pragma unroll
        for (int i = 0; i < 16; i++) {
            int f4 = tid + i * 64;
            float4 v = S4[f4];
            int row = f4 >> 7;
            int e0  = (f4 & 127) * 4;
            int a   = e0 >> 6;
            int k   = e0 & 63;
            float* dp = &s_sm[row * 520 + a * 65 + k];
            dp[0] = v.x; dp[1] = v.y; dp[2] = v.z; dp[3] = v.w;
        }
    }
    __syncthreads();

    const int r = tid >> 3, a = tid & 7;
    const float* srow = &s_sm[r * 520 + a * 65];

    float e[32];
    #pragma unroll
    for (int j = 0; j < 32; j++) e[j] = bt_sm[j];
    #pragma unroll 8
    for (int k = 0; k < 64; k++) {
        float sv = srow[k];
        const float4* wrow = (const float4*)&wt_sm[k * 32];
        #pragma unroll
        for (int j4 = 0; j4 < 8; j4++) {
            float4 w = wrow[j4];
            e[j4*4+0] += sv * w.x; e[j4*4+1] += sv * w.y;
            e[j4*4+2] += sv * w.z; e[j4*4+3] += sv * w.w;
        }
    }
    #pragma unroll
    for (int j = 0; j < 32; j++) e[j] = fmaxf(e[j], 0.f);

    float y[64];
    #pragma unroll
    for (int c = 0; c < 64; c++) y[c] = by_sm[c];
    #pragma unroll 4
    for (int j = 0; j < 32; j++) {
        float ev = e[j];
        const float4* wrow = (const float4*)&wy_sm[j * 64];
        #pragma unroll
        for (int c4 = 0; c4 < 16; c4++) {
            float4 w = wrow[c4];
            y[c4*4+0] += ev * w.x; y[c4*4+1] += ev * w.y;
            y[c4*4+2] += ev * w.z; y[c4*4+3] += ev * w.w;
        }
    }
    size_t row_g = (size_t)blockIdx.x * 8 + r;
    size_t off = row_g * SD + a * 64;
    #pragma unroll
    for (int c4 = 0; c4 < 16; c4++) {
        float o0 = fmaxf(y[c4*4+0], 0.f), o1 = fmaxf(y[c4*4+1], 0.f);
        float o2 = fmaxf(y[c4*4+2], 0.f), o3 = fmaxf(y[c4*4+3], 0.f);
        __nv_bfloat16 h0,l0,h1,l1,h2,l2,h3,l3;
        bf_split(o0,h0,l0); bf_split(o1,h1,l1); bf_split(o2,h2,l2); bf_split(o3,h3,l3);
        __nv_bfloat162 hA; hA.x=h0; hA.y=h1;
        __nv_bfloat162 hB; hB.x=h2; hB.y=h3;
        __nv_bfloat162 lA; lA.x=l0; lA.y=l1;
        __nv_bfloat162 lB; lB.x=l2; lB.y=l3;
        *(__nv_bfloat162*)&g_Yh[off + c4*4]     = hA;
        *(__nv_bfloat162*)&g_Yh[off + c4*4 + 2] = hB;
        *(__nv_bfloat162*)&g_Yl[off + c4*4]     = lA;
        *(__nv_bfloat162*)&g_Yl[off + c4*4 + 2] = lB;
    }
}

// =========================================================================
// gemm_mma: bf16 mma.sync, 3-product compensation, pre-split operands.
// BM=128, BN=64, BK=32, 256 threads = 8 warps (warp tile 32x32).
// Double-buffered cp.async pipeline.
// mode 0: C(B,576) = Y @ [W1a|Wfa|Wb1|Wv1] -> H1(bf16 h/l)/HF(bf16 h/l)/B1/Hv
// mode 1: blocks 0-3: W1 = abs(H1@W1b+b1b); block 4: WF = abs(HF@Wfb+bfb)
// =========================================================================
#define PITCH 40
#define A_BYTES (128 * PITCH * 2)     // 10240
#define B_BYTES (64 * PITCH * 2)      // 5120
#define STAGE   (2 * A_BYTES + 2 * B_BYTES)   // 30720
#define DSMEM   (2 * STAGE)                   // 61440

__global__ __launch_bounds__(256) void gemm_mma(
    int mode,
    const float* __restrict__ b1a, const float* __restrict__ bfa,
    const float* __restrict__ bb1, const float* __restrict__ bv1,
    const float* __restrict__ b1b, const float* __restrict__ bfb)
{
    extern __shared__ __align__(16) char dsm[];
    const uint32_t sbase = smem_u32(dsm);

    const int tid  = threadIdx.x;
    const int wid  = tid >> 5;
    const int lane = tid & 31;
    const int wm   = wid >> 1;          // 0..3 : m-quarter (32 rows)
    const int wn   = wid & 1;           // 0..1 : n-half (32 cols)
    const int nbase = blockIdx.x * 64;
    const int m0    = blockIdx.y * 128;

    const __nv_bfloat16 *Ah_p, *Al_p, *Bh_p, *Bl_p;
    int lda, ldb, NC;
    if (mode == 0) {
        Ah_p = g_Yh; Al_p = g_Yl; lda = 512;
        Bh_p = g_WT0h; Bl_p = g_WT0l; ldb = 512; NC = 16;
    } else {
        if (blockIdx.x == 4) { Ah_p = g_HFh; Al_p = g_HFl; }
        else                 { Ah_p = g_H1h; Al_p = g_H1l; }
        lda = 256;
        Bh_p = g_WT1h; Bl_p = g_WT1l; ldb = 256; NC = 8;
    }

    // per-thread staging coords
    const int ar0 = tid >> 2,  ak0 = (tid & 3) * 8;         // A chunk 0 (+256 for chunk 1)
    const int br0 = tid >> 2,  bk0 = (tid & 3) * 8;         // B (only tid<256 covers 64 rows x 4)

    auto issue = [&](int c) {
        const uint32_t st = sbase + (c & 1) * STAGE;
        // A hi/lo : 512 chunks each, 2 per thread
        #pragma unroll
        for (int i = 0; i < 2; i++) {
            int row = ar0 + i * 64;
            int k8  = ak0;
            uint32_t d = st + row * (PITCH*2) + k8 * 2;
            const __nv_bfloat16* sh = Ah_p + (size_t)(m0 + row) * lda + c * 32 + k8;
            const __nv_bfloat16* sl = Al_p + (size_t)(m0 + row) * lda + c * 32 + k8;
            CP16(d, sh);
            CP16(d + A_BYTES, sl);
        }
        // B hi/lo : 256 chunks each, 1 per thread
        {
            int n  = br0;
            int k8 = bk0;
            uint32_t d = st + 2 * A_BYTES + n * (PITCH*2) + k8 * 2;
            const __nv_bfloat16* sh = Bh_p + (size_t)(nbase + n) * ldb + c * 32 + k8;
            const __nv_bfloat16* sl = Bl_p + (size_t)(nbase + n) * ldb + c * 32 + k8;
            CP16(d, sh);
            CP16(d + B_BYTES, sl);
        }
        CP_COMMIT();
    };

    float acc[2][4][4];
    #pragma unroll
    for (int i = 0; i < 2; i++)
        #pragma unroll
        for (int j = 0; j < 4; j++)
            #pragma unroll
            for (int q = 0; q < 4; q++) acc[i][j][q] = 0.f;

    issue(0);

    const int g  = lane >> 3;
    const int li = lane & 7;

    for (int c = 0; c < NC; ++c) {
        if (c + 1 < NC) { issue(c + 1); CP_WAIT(1); }
        else            { CP_WAIT(0); }
        __syncthreads();

        const uint32_t st = sbase + (c & 1) * STAGE;
        const uint32_t sAh = st;
        const uint32_t sAl = st + A_BYTES;
        const uint32_t sBh = st + 2 * A_BYTES;
        const uint32_t sBl = st + 2 * A_BYTES + B_BYTES;

        #pragma unroll
        for (int ks = 0; ks < 2; ks++) {
            const int am = wm * 32 + (g & 1) * 8 + li;
            const int ak = (g >> 1) * 8 + ks * 16;
            const int bn = wn * 32 + (g >> 1) * 8 + li;
            const int bk = (g & 1) * 8 + ks * 16;

            uint32_t ah[2][4], al[2][4], bh[4][2], bl[4][2];
            #pragma unroll
            for (int mi = 0; mi < 2; mi++) {
                uint32_t a1 = sAh + ((am + mi * 16) * PITCH + ak) * 2;
                LDSM4(ah[mi][0], ah[mi][1], ah[mi][2], ah[mi][3], a1);
                uint32_t a2 = sAl + ((am + mi * 16) * PITCH + ak) * 2;
                LDSM4(al[mi][0], al[mi][1], al[mi][2], al[mi][3], a2);
            }
            #pragma unroll
            for (int bp = 0; bp < 2; bp++) {
                uint32_t a1 = sBh + ((bn + bp * 16) * PITCH + bk) * 2;
                LDSM4(bh[2*bp][0], bh[2*bp][1], bh[2*bp+1][0], bh[2*bp+1][1], a1);
                uint32_t a2 = sBl + ((bn + bp * 16) * PITCH + bk) * 2;
                LDSM4(bl[2*bp][0], bl[2*bp][1], bl[2*bp+1][0], bl[2*bp+1][1], a2);
            }
            #pragma unroll
            for (int mi = 0; mi < 2; mi++)
                #pragma unroll
                for (int ni = 0; ni < 4; ni++) {
                    MMA_BF16(acc[mi][ni], ah[mi], bh[ni]);
                    MMA_BF16(acc[mi][ni], ah[mi], bl[ni]);
                    MMA_BF16(acc[mi][ni], al[mi], bh[ni]);
                }
        }
        __syncthreads();
    }

    // ---- epilogue ----
    #pragma unroll
    for (int mi = 0; mi < 2; mi++) {
        #pragma unroll
        for (int ni = 0; ni < 4; ni++) {
            int m  = m0 + wm * 32 + mi * 16 + (lane >> 2);
            int ng = nbase + wn * 32 + ni * 8 + 2 * (lane & 3);
            #pragma unroll
            for (int half = 0; half < 2; half++) {
                int mm = m + half * 8;
                float x0 = acc[mi][ni][half * 2 + 0];
                float x1 = acc[mi][ni][half * 2 + 1];
                if (mode == 0) {
                    if (ng < 256) {
                        float2 b = *(const float2*)&b1a[ng];
                        float o0 = fmaxf(x0 + b.x, 0.f), o1 = fmaxf(x1 + b.y, 0.f);
                        __nv_bfloat16 h0,l0,h1,l1;
                        bf_split(o0,h0,l0); bf_split(o1,h1,l1);
                        __nv_bfloat162 hv; hv.x=h0; hv.y=h1;
                        __nv_bfloat162 lv; lv.x=l0; lv.y=l1;
                        *(__nv_bfloat162*)&g_H1h[(size_t)mm * 256 + ng] = hv;
                        *(__nv_bfloat162*)&g_H1l[(size_t)mm * 256 + ng] = lv;
                    } else if (ng < 512) {
                        int nl = ng - 256;
                        float2 b = *(const float2*)&bfa[nl];
                        float o0 = fmaxf(x0 + b.x, 0.f), o1 = fmaxf(x1 + b.y, 0.f);
                        __nv_bfloat16 h0,l0,h1,l1;
                        bf_split(o0,h0,l0); bf_split(o1,h1,l1);
                        __nv_bfloat162 hv; hv.x=h0; hv.y=h1;
                        __nv_bfloat162 lv; lv.x=l0; lv.y=l1;
                        *(__nv_bfloat162*)&g_HFh[(size_t)mm * 256 + nl] = hv;
                        *(__nv_bfloat162*)&g_HFl[(size_t)mm * 256 + nl] = lv;
                    } else if (ng < 544) {
                        int nl = ng - 512;
                        float2 b = *(const float2*)&bb1[nl];
                        float2 o = make_float2(x0 + b.x, x1 + b.y);
                        *(float2*)&g_B1[(size_t)mm * 32 + nl] = o;
                    } else {
                        int nl = ng - 544;
                        float2 b = *(const float2*)&bv1[nl];
                        float2 o = make_float2(fmaxf(x0 + b.x, 0.f), fmaxf(x1 + b.y, 0.f));
                        *(float2*)&g_Hv[(size_t)mm * 32 + nl] = o;
                    }
                } else {
                    if (nbase < 256) {
                        float2 b = *(const float2*)&b1b[ng];
                        float2 o = make_float2(fabsf(x0 + b.x), fabsf(x1 + b.y));
                        *(float2*)&g_W1[(size_t)mm * 256 + ng] = o;
                    } else {
                        int nl = ng - 256;
                        if (nl < 32) {
                            float2 b = *(const float2*)&bfb[nl];
                            float2 o = make_float2(fabsf(x0 + b.x), fabsf(x1 + b.y));
                            *(float2*)&g_WF[(size_t)mm * 32 + nl] = o;
                        }
                    }
                }
            }
        }
    }
}

// =========================================================================
// K4: final fused epilogue. One warp per row; lane = EMB index e.
// =========================================================================
__device__ __forceinline__ float wred(float v) {
    #pragma unroll
    for (int o = 16; o > 0; o >>= 1) v += __shfl_xor_sync(0xFFFFFFFFu, v, o);
    return v;
}

__global__ __launch_bounds__(256) void k4_final(
    const float* __restrict__ agent_qs,
    const float* __restrict__ Wv2, const float* __restrict__ bv2,
    float* __restrict__ out)
{
    const int w = threadIdx.x >> 5, lane = threadIdx.x & 31;
    const size_t r = (size_t)blockIdx.x * 8 + w;

    const float wv2v = Wv2[lane];

    float q[8];
    #pragma unroll
    for (int a = 0; a < 8; a++) q[a] = agent_qs[r * 8 + a];

    float w1r[8];
    const float* w1p = g_W1 + r * 256;
    #pragma unroll
    for (int a = 0; a < 8; a++) w1r[a] = w1p[a * 32 + lane];

    float x = g_B1[r * 32 + lane];
    #pragma unroll
    for (int a = 0; a < 8; a++) x += q[a] * w1r[a];
    const float h    = (x > 0.f) ? x : expm1f(x);
    const float delu = (h < 0.f) ? expf(h) : 1.f;

    const float wf = g_WF[r * 32 + lane];
    const float hv = g_Hv[r * 32 + lane];

    const float vsum = wred(hv * wv2v);
    const float qt   = wred(h * wf);
    if (lane == 0) out[r] = qt + vsum + bv2[0];

    const float t = delu * wf;
    float* gout = out + BTOT;
    #pragma unroll
    for (int a = 0; a < 8; a++) {
        float s = wred(w1r[a] * t);
        if (lane == a) gout[r * 8 + a] = s;
    }
}

// =========================================================================
extern "C" void kernel_launch(void* const* d_in, const int* in_sizes, int n_in,
                              void* d_out, int out_size)
{
    (void)in_sizes; (void)n_in; (void)out_size;
    const float* agent_qs = (const float*)d_in[0];
    const float* states = (const float*)d_in[2];   // d_in[1]=hist, d_in[3]=obs unused
    const float* W_tok  = (const float*)d_in[4];
    const float* b_tok  = (const float*)d_in[5];
    const float* W_yfc  = (const float*)d_in[6];
    const float* b_yfc  = (const float*)d_in[7];
    const float* W1a    = (const float*)d_in[8];
    const float* b1a    = (const float*)d_in[9];
    const float* W1b    = (const float*)d_in[10];
    const float* b1b    = (const float*)d_in[11];
    const float* Wfa    = (const float*)d_in[12];
    const float* bfa    = (const float*)d_in[13];
    const float* Wfb    = (const float*)d_in[14];
    const float* bfb    = (const float*)d_in[15];
    const float* Wb1    = (const float*)d_in[16];
    const float* bb1    = (const float*)d_in[17];
    const float* Wv1    = (const float*)d_in[18];
    const float* bv1    = (const float*)d_in[19];
    const float* Wv2    = (const float*)d_in[20];
    const float* bv2    = (const float*)d_in[21];
    float* out = (float*)d_out;

    cudaFuncSetAttribute(gemm_mma, cudaFuncAttributeMaxDynamicSharedMemorySize, DSMEM);

    prep_split<<<1472, 256>>>(W1a, Wfa, Wb1, Wv1, W1b, Wfb);
    k1_embed<<<BTOT / 8, 64>>>(states, W_tok, b_tok, W_yfc, b_yfc);
    gemm_mma<<<dim3(9, BTOT / 128), 256, DSMEM>>>(0, b1a, bfa, bb1, bv1, b1b, bfb);
    gemm_mma<<<dim3(5, BTOT / 128), 256, DSMEM>>>(1, b1a, bfa, bb1, bv1, b1b, bfb);
    k4_final<<<BTOT / 8, 256>>>(agent_qs, Wv2, bv2, out);
}